// round 7
// baseline (speedup 1.0000x reference)
#include <cuda_runtime.h>
#include <cuda_fp16.h>
#include <cuda_bf16.h>
#include <mma.h>
using namespace nvcuda;

// Problem constants (fixed dataset)
#define NN 100000      // nodes
#define NE 1600000     // edges
#define IN_F 128
#define H_F 64
#define C_F 16
#define NBLK ((NN + 1023) / 1024)   // 98 scan blocks

// Scratch (static device arrays; no allocation allowed)
__device__ uint4 g_H1h[NN * 8];       // X @ W1, fp16 (64 halves = 8 uint4 per row)
__device__ uint4 g_H2h[NN * 2];       // fused layer-2 features, fp16 (16 halves)
__device__ int   g_deg[NN];           // in-degree per dst (zeroed at end of agg2)
__device__ int   g_off[NN];           // CSR row offsets
__device__ int   g_cursor[NN];        // fill cursor for reorder
__device__ int   g_blocksum[NBLK];
__device__ int   g_flag[NBLK];        // publication flags (zeroed at end of agg2)
__device__ int2  g_csr[NE];           // (src, weight-bits) sorted by dst

// ---------------------------------------------------------------------------
__global__ void hist_kernel(const int* __restrict__ edst) {
    int e = blockIdx.x * blockDim.x + threadIdx.x;
    if (e < NE) atomicAdd(&g_deg[__ldg(&edst[e])], 1);
}

// Fused scan: per-block exclusive scan (1024/block) + cross-block lookback.
// All 98 blocks co-resident (148 SMs): publish-before-spin => deadlock-free.
__global__ __launch_bounds__(1024) void scan_fused_kernel() {
    __shared__ int warpsums[32];
    __shared__ int s_part[32];
    __shared__ int s_boff;
    const int t = threadIdx.x, lane = t & 31, wid = t >> 5;
    const int b = blockIdx.x;
    const int i = b * 1024 + t;

    int v = (i < NN) ? g_deg[i] : 0;
    int s = v;
    #pragma unroll
    for (int o = 1; o < 32; o <<= 1) {
        int nv = __shfl_up_sync(0xffffffffu, s, o);
        if (lane >= o) s += nv;
    }
    if (lane == 31) warpsums[wid] = s;
    __syncthreads();
    if (wid == 0) {
        int ws = warpsums[lane];
        int t2 = ws;
        #pragma unroll
        for (int o = 1; o < 32; o <<= 1) {
            int nv = __shfl_up_sync(0xffffffffu, t2, o);
            if (lane >= o) t2 += nv;
        }
        warpsums[lane] = t2 - ws;
        if (lane == 31) {
            g_blocksum[b] = t2;
            __threadfence();
            atomicExch(&g_flag[b], 1);
        }
    }
    __syncthreads();

    int part = 0;
    if (t < b) {
        while (atomicAdd(&g_flag[t], 0) == 0) { }
        part = g_blocksum[t];
    }
    #pragma unroll
    for (int o = 16; o > 0; o >>= 1) part += __shfl_down_sync(0xffffffffu, part, o);
    if (lane == 0) s_part[wid] = part;
    __syncthreads();
    if (t == 0) {
        int acc = 0;
        #pragma unroll
        for (int w = 0; w < 32; w++) acc += s_part[w];
        s_boff = acc;
    }
    __syncthreads();

    if (i < NN) {
        int val = warpsums[wid] + s - v + s_boff;
        g_off[i] = val;
        g_cursor[i] = val;
    }
}

__global__ void reorder_kernel(const int* __restrict__ esrc,
                               const int* __restrict__ edst,
                               const float* __restrict__ ew) {
    int e = blockIdx.x * blockDim.x + threadIdx.x;
    if (e < NE) {
        int d = __ldg(&edst[e]);
        int p = atomicAdd(&g_cursor[d], 1);
        g_csr[p] = make_int2(__ldg(&esrc[e]), __float_as_int(__ldg(&ew[e])));
    }
}

// ---------------------------------------------------------------------------
// GEMM1 (tensor cores): H1[NN,64] = X[NN,128] @ W1[128,64]
#define XS_LD 136
#define WS_LD 72
__global__ __launch_bounds__(256) void gemm1_kernel(
    const float* __restrict__ X, const float* __restrict__ W1)
{
    __shared__ __align__(16) char smbuf[64 * XS_LD * 2 + 128 * WS_LD * 2];
    __half* Xs = reinterpret_cast<__half*>(smbuf);
    __half* Ws = reinterpret_cast<__half*>(smbuf + 64 * XS_LD * 2);
    float*  Cs = reinterpret_cast<float*>(smbuf);

    const int t = threadIdx.x;
    const int row0 = blockIdx.x * 64;

    const float4* Xv = reinterpret_cast<const float4*>(X);
    #pragma unroll
    for (int i = 0; i < 8; i++) {
        int idx = t + i * 256;
        int r = idx >> 5;
        int c4 = idx & 31;
        int grow = row0 + r;
        float4 v = make_float4(0.f, 0.f, 0.f, 0.f);
        if (grow < NN) v = Xv[(long long)grow * 32 + c4];
        __half2* dst = reinterpret_cast<__half2*>(&Xs[r * XS_LD + c4 * 4]);
        dst[0] = __floats2half2_rn(v.x, v.y);
        dst[1] = __floats2half2_rn(v.z, v.w);
    }
    const float4* Wv = reinterpret_cast<const float4*>(W1);
    #pragma unroll
    for (int i = 0; i < 8; i++) {
        int idx = t + i * 256;
        int k = idx >> 4;
        int c4 = idx & 15;
        float4 v = Wv[k * 16 + c4];
        __half2* dst = reinterpret_cast<__half2*>(&Ws[k * WS_LD + c4 * 4]);
        dst[0] = __floats2half2_rn(v.x, v.y);
        dst[1] = __floats2half2_rn(v.z, v.w);
    }
    __syncthreads();

    const int w = t >> 5;
    const int m_tile = w >> 1;
    const int n0 = (w & 1) * 32;

    wmma::fragment<wmma::accumulator, 16, 16, 16, float> acc0, acc1;
    wmma::fill_fragment(acc0, 0.f);
    wmma::fill_fragment(acc1, 0.f);

    #pragma unroll
    for (int k = 0; k < 8; k++) {
        wmma::fragment<wmma::matrix_a, 16, 16, 16, __half, wmma::row_major> a;
        wmma::load_matrix_sync(a, Xs + m_tile * 16 * XS_LD + k * 16, XS_LD);
        wmma::fragment<wmma::matrix_b, 16, 16, 16, __half, wmma::row_major> b0, b1;
        wmma::load_matrix_sync(b0, Ws + k * 16 * WS_LD + n0, WS_LD);
        wmma::load_matrix_sync(b1, Ws + k * 16 * WS_LD + n0 + 16, WS_LD);
        wmma::mma_sync(acc0, a, b0, acc0);
        wmma::mma_sync(acc1, a, b1, acc1);
    }
    __syncthreads();

    wmma::store_matrix_sync(Cs + m_tile * 16 * 64 + n0, acc0, 64, wmma::mem_row_major);
    wmma::store_matrix_sync(Cs + m_tile * 16 * 64 + n0 + 16, acc1, 64, wmma::mem_row_major);
    __syncthreads();

    __half2* H1 = reinterpret_cast<__half2*>(g_H1h);
    #pragma unroll
    for (int i = 0; i < 8; i++) {
        int idx = t + i * 256;
        int r = idx >> 5;
        int c2 = idx & 31;
        int grow = row0 + r;
        if (grow < NN) {
            float lo = Cs[r * 64 + c2 * 2];
            float hi = Cs[r * 64 + c2 * 2 + 1];
            H1[grow * 32 + c2] = __floats2half2_rn(lo, hi);
        }
    }
}

// ---------------------------------------------------------------------------
// agg1 + GEMM2, warp-per-node: zero degree divergence.
// Lane owns one 4B word (2 halves) of the 128B H1 row. NN = 12500*8 exactly.
__global__ __launch_bounds__(256) void agg1_fused_kernel(
    const float* __restrict__ b1, const float* __restrict__ W2)
{
    __shared__ float Ws[64 * 16];
    __shared__ float hbuf[8][64];

    const int t = threadIdx.x;
    #pragma unroll
    for (int i = 0; i < 4; i++) Ws[t + i * 256] = W2[t + i * 256];
    __syncthreads();

    const int wid = t >> 5, lane = t & 31;
    const int n = blockIdx.x * 8 + wid;
    const int start = g_off[n];
    const int cnt   = g_deg[n];
    const unsigned int* H1w = reinterpret_cast<const unsigned int*>(g_H1h);

    float a0 = 0.f, a1 = 0.f;
    int j = 0;
    for (; j + 4 <= cnt; j += 4) {
        int2 e0 = __ldg(&g_csr[start + j]);
        int2 e1 = __ldg(&g_csr[start + j + 1]);
        int2 e2 = __ldg(&g_csr[start + j + 2]);
        int2 e3 = __ldg(&g_csr[start + j + 3]);
        unsigned int v0 = __ldg(&H1w[e0.x * 32 + lane]);
        unsigned int v1 = __ldg(&H1w[e1.x * 32 + lane]);
        unsigned int v2 = __ldg(&H1w[e2.x * 32 + lane]);
        unsigned int v3 = __ldg(&H1w[e3.x * 32 + lane]);
        float2 f0 = __half22float2(*reinterpret_cast<__half2*>(&v0));
        float2 f1 = __half22float2(*reinterpret_cast<__half2*>(&v1));
        float2 f2 = __half22float2(*reinterpret_cast<__half2*>(&v2));
        float2 f3 = __half22float2(*reinterpret_cast<__half2*>(&v3));
        float w0 = __int_as_float(e0.y), w1 = __int_as_float(e1.y);
        float w2 = __int_as_float(e2.y), w3 = __int_as_float(e3.y);
        a0 = fmaf(f0.x, w0, a0); a1 = fmaf(f0.y, w0, a1);
        a0 = fmaf(f1.x, w1, a0); a1 = fmaf(f1.y, w1, a1);
        a0 = fmaf(f2.x, w2, a0); a1 = fmaf(f2.y, w2, a1);
        a0 = fmaf(f3.x, w3, a0); a1 = fmaf(f3.y, w3, a1);
    }
    for (; j < cnt; j++) {
        int2 ed = __ldg(&g_csr[start + j]);
        unsigned int v = __ldg(&H1w[ed.x * 32 + lane]);
        float2 f = __half22float2(*reinterpret_cast<__half2*>(&v));
        float w = __int_as_float(ed.y);
        a0 = fmaf(f.x, w, a0); a1 = fmaf(f.y, w, a1);
    }

    // bias + relu; publish 64-vec to smem
    float2 b = __ldg(&reinterpret_cast<const float2*>(b1)[lane]);
    a0 = fmaxf(a0 + b.x, 0.f);
    a1 = fmaxf(a1 + b.y, 0.f);
    reinterpret_cast<float2*>(&hbuf[wid][0])[lane] = make_float2(a0, a1);
    __syncwarp();

    // matvec: lane = {half: lane>>4, col: lane&15}; split-k + butterfly reduce
    const int half = lane >> 4, col = lane & 15;
    const float* h = hbuf[wid];
    float p = 0.f;
    #pragma unroll
    for (int k = 0; k < 32; k++) {
        int kk = half * 32 + k;
        p = fmaf(h[kk], Ws[kk * 16 + col], p);
    }
    p += __shfl_xor_sync(0xffffffffu, p, 16);
    __half* H2 = reinterpret_cast<__half*>(g_H2h);
    if (lane < 16) H2[n * 16 + col] = __float2half_rn(p);
}

// ---------------------------------------------------------------------------
// agg2, warp-per-node with 4 edge-slots: out[n] = sum_in H2[src]*w + b2
// lane = {slot: lane>>3, sub: lane&7}; slot handles edge j0+slot, sub owns
// half2 index sub of the 16-half row. Also restores g_deg/g_flag = 0.
__global__ __launch_bounds__(256) void agg2_kernel(
    const float* __restrict__ b2, float* __restrict__ out)
{
    const int t = threadIdx.x;
    const int wid = t >> 5, lane = t & 31;
    const int n = blockIdx.x * 8 + wid;
    const int slot = lane >> 3, sub = lane & 7;
    const int start = g_off[n];
    const int cnt   = g_deg[n];
    const unsigned int* H2w = reinterpret_cast<const unsigned int*>(g_H2h);

    float a0 = 0.f, a1 = 0.f;
    for (int j0 = 0; j0 < cnt; j0 += 4) {
        int j = j0 + slot;
        if (j < cnt) {
            int2 ed = __ldg(&g_csr[start + j]);
            unsigned int v = __ldg(&H2w[ed.x * 8 + sub]);
            float2 f = __half22float2(*reinterpret_cast<__half2*>(&v));
            float w = __int_as_float(ed.y);
            a0 = fmaf(f.x, w, a0); a1 = fmaf(f.y, w, a1);
        }
    }
    // reduce across the 4 slots
    a0 += __shfl_down_sync(0xffffffffu, a0, 16);
    a1 += __shfl_down_sync(0xffffffffu, a1, 16);
    a0 += __shfl_down_sync(0xffffffffu, a0, 8);
    a1 += __shfl_down_sync(0xffffffffu, a1, 8);

    if (lane < 8) {
        float2 b = __ldg(&reinterpret_cast<const float2*>(b2)[sub]);
        reinterpret_cast<float2*>(out)[n * 8 + sub] = make_float2(a0 + b.x, a1 + b.y);
    }

    // restore scratch state for the next replay
    if (lane == 0) g_deg[n] = 0;
    if (blockIdx.x == 0 && t < NBLK) g_flag[t] = 0;
}

// ---------------------------------------------------------------------------
extern "C" void kernel_launch(void* const* d_in, const int* in_sizes, int n_in,
                              void* d_out, int out_size)
{
    const float* X    = (const float*)d_in[0];
    const float* ew   = (const float*)d_in[1];
    const float* W1   = (const float*)d_in[2];
    const float* b1   = (const float*)d_in[3];
    const float* W2   = (const float*)d_in[4];
    const float* b2   = (const float*)d_in[5];
    const int*   esrc = (const int*)d_in[6];
    const int*   edst = (const int*)d_in[7];
    float* out = (float*)d_out;

    static cudaStream_t s1 = 0;
    static cudaEvent_t eFork = 0, eJoin = 0;
    static bool init_done = false;
    if (!init_done) {
        cudaStreamCreateWithFlags(&s1, cudaStreamNonBlocking);
        cudaEventCreateWithFlags(&eFork, cudaEventDisableTiming);
        cudaEventCreateWithFlags(&eJoin, cudaEventDisableTiming);
        init_done = true;
    }

    // Fork: gemm1 (independent of CSR build) on s1
    cudaEventRecord(eFork, 0);
    cudaStreamWaitEvent(s1, eFork, 0);
    gemm1_kernel<<<(NN + 63) / 64, 256, 0, s1>>>(X, W1);

    // CSR build on main stream (g_deg/g_flag pre-zeroed by previous call / load)
    hist_kernel<<<(NE + 255) / 256, 256>>>(edst);
    scan_fused_kernel<<<NBLK, 1024>>>();
    reorder_kernel<<<(NE + 255) / 256, 256>>>(esrc, edst, ew);

    // Join: aggregation needs both H1 and the CSR
    cudaEventRecord(eJoin, s1);
    cudaStreamWaitEvent(0, eJoin, 0);

    agg1_fused_kernel<<<NN / 8, 256>>>(b1, W2);
    agg2_kernel<<<NN / 8, 256>>>(b2, out);
}

// round 8
// speedup vs baseline: 1.1905x; 1.1905x over previous
#include <cuda_runtime.h>
#include <cuda_fp16.h>
#include <cuda_bf16.h>
#include <mma.h>
using namespace nvcuda;

// Problem constants (fixed dataset)
#define NN 100000      // nodes
#define NE 1600000     // edges
#define IN_F 128
#define H_F 64
#define C_F 16
#define NBLK ((NN + 1023) / 1024)   // 98 scan blocks

// Scratch (static device arrays; no allocation allowed)
__device__ uint4 g_H1h[NN * 8];       // X @ W1, fp16 (64 halves = 8 uint4 per row)
__device__ uint4 g_H2h[NN * 2];       // fused layer-2 features, fp16 (16 halves)
__device__ int   g_deg[NN];           // in-degree per dst (zeroed at end of agg2)
__device__ int   g_off[NN];           // CSR row offsets
__device__ int   g_cursor[NN];        // fill cursor for reorder
__device__ int   g_blocksum[NBLK];
__device__ int   g_flag[NBLK];        // publication flags (zeroed at end of agg2)
__device__ int2  g_csr[NE];           // (src, weight-bits) sorted by dst

// ---------------------------------------------------------------------------
__global__ void hist_kernel(const int* __restrict__ edst) {
    int e = blockIdx.x * blockDim.x + threadIdx.x;
    if (e < NE) atomicAdd(&g_deg[__ldg(&edst[e])], 1);
}

// Fused scan: per-block exclusive scan (1024/block) + cross-block lookback.
// All 98 blocks co-resident (148 SMs): publish-before-spin => deadlock-free.
__global__ __launch_bounds__(1024) void scan_fused_kernel() {
    __shared__ int warpsums[32];
    __shared__ int s_part[32];
    __shared__ int s_boff;
    const int t = threadIdx.x, lane = t & 31, wid = t >> 5;
    const int b = blockIdx.x;
    const int i = b * 1024 + t;

    int v = (i < NN) ? g_deg[i] : 0;
    int s = v;
    #pragma unroll
    for (int o = 1; o < 32; o <<= 1) {
        int nv = __shfl_up_sync(0xffffffffu, s, o);
        if (lane >= o) s += nv;
    }
    if (lane == 31) warpsums[wid] = s;
    __syncthreads();
    if (wid == 0) {
        int ws = warpsums[lane];
        int t2 = ws;
        #pragma unroll
        for (int o = 1; o < 32; o <<= 1) {
            int nv = __shfl_up_sync(0xffffffffu, t2, o);
            if (lane >= o) t2 += nv;
        }
        warpsums[lane] = t2 - ws;
        if (lane == 31) {
            g_blocksum[b] = t2;
            __threadfence();
            atomicExch(&g_flag[b], 1);
        }
    }
    __syncthreads();

    int part = 0;
    if (t < b) {
        while (atomicAdd(&g_flag[t], 0) == 0) { }
        part = g_blocksum[t];
    }
    #pragma unroll
    for (int o = 16; o > 0; o >>= 1) part += __shfl_down_sync(0xffffffffu, part, o);
    if (lane == 0) s_part[wid] = part;
    __syncthreads();
    if (t == 0) {
        int acc = 0;
        #pragma unroll
        for (int w = 0; w < 32; w++) acc += s_part[w];
        s_boff = acc;
    }
    __syncthreads();

    if (i < NN) {
        int val = warpsums[wid] + s - v + s_boff;
        g_off[i] = val;
        g_cursor[i] = val;
    }
}

// reorder: 4 edges per thread, vectorized loads, 4 independent atomic chains.
// NE = 400000 * 4 exactly.
__global__ __launch_bounds__(256) void reorder_kernel(
    const int* __restrict__ esrc, const int* __restrict__ edst,
    const float* __restrict__ ew)
{
    int i = blockIdx.x * blockDim.x + threadIdx.x;
    if (i >= NE / 4) return;
    int4   s = __ldg(&reinterpret_cast<const int4*>(esrc)[i]);
    int4   d = __ldg(&reinterpret_cast<const int4*>(edst)[i]);
    float4 w = __ldg(&reinterpret_cast<const float4*>(ew)[i]);
    int p0 = atomicAdd(&g_cursor[d.x], 1);
    int p1 = atomicAdd(&g_cursor[d.y], 1);
    int p2 = atomicAdd(&g_cursor[d.z], 1);
    int p3 = atomicAdd(&g_cursor[d.w], 1);
    g_csr[p0] = make_int2(s.x, __float_as_int(w.x));
    g_csr[p1] = make_int2(s.y, __float_as_int(w.y));
    g_csr[p2] = make_int2(s.z, __float_as_int(w.z));
    g_csr[p3] = make_int2(s.w, __float_as_int(w.w));
}

// ---------------------------------------------------------------------------
// GEMM1 (tensor cores): H1[NN,64] = X[NN,128] @ W1[128,64]
#define XS_LD 136
#define WS_LD 72
__global__ __launch_bounds__(256) void gemm1_kernel(
    const float* __restrict__ X, const float* __restrict__ W1)
{
    __shared__ __align__(16) char smbuf[64 * XS_LD * 2 + 128 * WS_LD * 2];
    __half* Xs = reinterpret_cast<__half*>(smbuf);
    __half* Ws = reinterpret_cast<__half*>(smbuf + 64 * XS_LD * 2);
    float*  Cs = reinterpret_cast<float*>(smbuf);

    const int t = threadIdx.x;
    const int row0 = blockIdx.x * 64;

    const float4* Xv = reinterpret_cast<const float4*>(X);
    #pragma unroll
    for (int i = 0; i < 8; i++) {
        int idx = t + i * 256;
        int r = idx >> 5;
        int c4 = idx & 31;
        int grow = row0 + r;
        float4 v = make_float4(0.f, 0.f, 0.f, 0.f);
        if (grow < NN) v = Xv[(long long)grow * 32 + c4];
        __half2* dst = reinterpret_cast<__half2*>(&Xs[r * XS_LD + c4 * 4]);
        dst[0] = __floats2half2_rn(v.x, v.y);
        dst[1] = __floats2half2_rn(v.z, v.w);
    }
    const float4* Wv = reinterpret_cast<const float4*>(W1);
    #pragma unroll
    for (int i = 0; i < 8; i++) {
        int idx = t + i * 256;
        int k = idx >> 4;
        int c4 = idx & 15;
        float4 v = Wv[k * 16 + c4];
        __half2* dst = reinterpret_cast<__half2*>(&Ws[k * WS_LD + c4 * 4]);
        dst[0] = __floats2half2_rn(v.x, v.y);
        dst[1] = __floats2half2_rn(v.z, v.w);
    }
    __syncthreads();

    const int w = t >> 5;
    const int m_tile = w >> 1;
    const int n0 = (w & 1) * 32;

    wmma::fragment<wmma::accumulator, 16, 16, 16, float> acc0, acc1;
    wmma::fill_fragment(acc0, 0.f);
    wmma::fill_fragment(acc1, 0.f);

    #pragma unroll
    for (int k = 0; k < 8; k++) {
        wmma::fragment<wmma::matrix_a, 16, 16, 16, __half, wmma::row_major> a;
        wmma::load_matrix_sync(a, Xs + m_tile * 16 * XS_LD + k * 16, XS_LD);
        wmma::fragment<wmma::matrix_b, 16, 16, 16, __half, wmma::row_major> b0, b1;
        wmma::load_matrix_sync(b0, Ws + k * 16 * WS_LD + n0, WS_LD);
        wmma::load_matrix_sync(b1, Ws + k * 16 * WS_LD + n0 + 16, WS_LD);
        wmma::mma_sync(acc0, a, b0, acc0);
        wmma::mma_sync(acc1, a, b1, acc1);
    }
    __syncthreads();

    wmma::store_matrix_sync(Cs + m_tile * 16 * 64 + n0, acc0, 64, wmma::mem_row_major);
    wmma::store_matrix_sync(Cs + m_tile * 16 * 64 + n0 + 16, acc1, 64, wmma::mem_row_major);
    __syncthreads();

    __half2* H1 = reinterpret_cast<__half2*>(g_H1h);
    #pragma unroll
    for (int i = 0; i < 8; i++) {
        int idx = t + i * 256;
        int r = idx >> 5;
        int c2 = idx & 31;
        int grow = row0 + r;
        if (grow < NN) {
            float lo = Cs[r * 64 + c2 * 2];
            float hi = Cs[r * 64 + c2 * 2 + 1];
            H1[grow * 32 + c2] = __floats2half2_rn(lo, hi);
        }
    }
}

// ---------------------------------------------------------------------------
__device__ __forceinline__ void fma_h8(float* acc, uint4 v, float w) {
    const __half2* hp = reinterpret_cast<const __half2*>(&v);
    #pragma unroll
    for (int i = 0; i < 4; i++) {
        float2 f = __half22float2(hp[i]);
        acc[2*i]   = fmaf(f.x, w, acc[2*i]);
        acc[2*i+1] = fmaf(f.y, w, acc[2*i+1]);
    }
}

// Fused aggregation + GEMM2 (R5 layout: 8 threads/node, LDG.128 gathers).
// NN*8 = 800000 = 3125*256 exactly.
__global__ __launch_bounds__(256) void agg1_fused_kernel(
    const float* __restrict__ b1, const float* __restrict__ W2)
{
    __shared__ float Ws[64 * 16];
    __shared__ float b1s[64];
    __shared__ float hbuf[32 * 68];

    const int t = threadIdx.x;
    #pragma unroll
    for (int i = 0; i < 4; i++) Ws[t + i * 256] = W2[t + i * 256];
    if (t < 64) b1s[t] = b1[t];
    __syncthreads();

    const int gt = blockIdx.x * 256 + t;
    const int n = gt >> 3;
    const int q = gt & 7;
    const int g = t >> 3;

    const int start = g_off[n];
    const int cnt   = g_deg[n];

    float acc[8];
    #pragma unroll
    for (int i = 0; i < 8; i++) acc[i] = 0.f;

    int j = 0;
    if ((start & 1) && j < cnt) {
        int2 ed = __ldg(&g_csr[start]);
        fma_h8(acc, __ldg(&g_H1h[ed.x * 8 + q]), __int_as_float(ed.y));
        j = 1;
    }
    const int4* csr4 = reinterpret_cast<const int4*>(g_csr + start + j);
    int rem = cnt - j;
    int quads = rem >> 2;
    for (int k = 0; k < quads; k++) {
        int4 eA = __ldg(&csr4[2*k]);
        int4 eB = __ldg(&csr4[2*k + 1]);
        uint4 v0 = __ldg(&g_H1h[eA.x * 8 + q]);
        uint4 v1 = __ldg(&g_H1h[eA.z * 8 + q]);
        uint4 v2 = __ldg(&g_H1h[eB.x * 8 + q]);
        uint4 v3 = __ldg(&g_H1h[eB.z * 8 + q]);
        fma_h8(acc, v0, __int_as_float(eA.y));
        fma_h8(acc, v1, __int_as_float(eA.w));
        fma_h8(acc, v2, __int_as_float(eB.y));
        fma_h8(acc, v3, __int_as_float(eB.w));
    }
    j += quads << 2;
    for (; j < cnt; j++) {
        int2 ed = __ldg(&g_csr[start + j]);
        fma_h8(acc, __ldg(&g_H1h[ed.x * 8 + q]), __int_as_float(ed.y));
    }

    #pragma unroll
    for (int i = 0; i < 8; i++) {
        float h = fmaxf(acc[i] + b1s[q * 8 + i], 0.f);
        hbuf[g * 68 + q * 8 + i] = h;
    }
    __syncwarp();

    float p0 = 0.f, p1 = 0.f;
    const float4* hb4 = reinterpret_cast<const float4*>(&hbuf[g * 68]);
    const float2* Ws2 = reinterpret_cast<const float2*>(Ws);
    #pragma unroll
    for (int k4 = 0; k4 < 16; k4++) {
        float4 hv = hb4[k4];
        float2 w0 = Ws2[(k4 * 4 + 0) * 8 + q];
        float2 w1 = Ws2[(k4 * 4 + 1) * 8 + q];
        float2 w2 = Ws2[(k4 * 4 + 2) * 8 + q];
        float2 w3 = Ws2[(k4 * 4 + 3) * 8 + q];
        p0 = fmaf(hv.x, w0.x, p0); p1 = fmaf(hv.x, w0.y, p1);
        p0 = fmaf(hv.y, w1.x, p0); p1 = fmaf(hv.y, w1.y, p1);
        p0 = fmaf(hv.z, w2.x, p0); p1 = fmaf(hv.z, w2.y, p1);
        p0 = fmaf(hv.w, w3.x, p0); p1 = fmaf(hv.w, w3.y, p1);
    }
    reinterpret_cast<__half2*>(g_H2h)[n * 8 + q] = __floats2half2_rn(p0, p1);
}

// ---------------------------------------------------------------------------
// Aggregation layer 2 (R5 layout: 2 threads/node, LDG.128 gathers).
// Also restores g_deg/g_flag = 0 for the next replay.
__global__ __launch_bounds__(256) void agg2_kernel(
    const float* __restrict__ b2, float* __restrict__ out)
{
    int gt = blockIdx.x * blockDim.x + threadIdx.x;
    int n = gt >> 1;
    int q = gt & 1;
    if (n >= NN) return;
    const int start = g_off[n];
    const int cnt   = g_deg[n];

    float acc[8];
    #pragma unroll
    for (int i = 0; i < 8; i++) acc[i] = 0.f;

    int j = 0;
    if ((start & 1) && j < cnt) {
        int2 ed = __ldg(&g_csr[start]);
        fma_h8(acc, __ldg(&g_H2h[ed.x * 2 + q]), __int_as_float(ed.y));
        j = 1;
    }
    const int4* csr4 = reinterpret_cast<const int4*>(g_csr + start + j);
    int rem = cnt - j;
    int quads = rem >> 2;
    for (int k = 0; k < quads; k++) {
        int4 eA = __ldg(&csr4[2*k]);
        int4 eB = __ldg(&csr4[2*k + 1]);
        uint4 v0 = __ldg(&g_H2h[eA.x * 2 + q]);
        uint4 v1 = __ldg(&g_H2h[eA.z * 2 + q]);
        uint4 v2 = __ldg(&g_H2h[eB.x * 2 + q]);
        uint4 v3 = __ldg(&g_H2h[eB.z * 2 + q]);
        fma_h8(acc, v0, __int_as_float(eA.y));
        fma_h8(acc, v1, __int_as_float(eA.w));
        fma_h8(acc, v2, __int_as_float(eB.y));
        fma_h8(acc, v3, __int_as_float(eB.w));
    }
    j += quads << 2;
    for (; j < cnt; j++) {
        int2 ed = __ldg(&g_csr[start + j]);
        fma_h8(acc, __ldg(&g_H2h[ed.x * 2 + q]), __int_as_float(ed.y));
    }

    const float4* b2v = reinterpret_cast<const float4*>(b2);
    float4 ba = __ldg(&b2v[q * 2]);
    float4 bb = __ldg(&b2v[q * 2 + 1]);
    float4 o0 = make_float4(acc[0] + ba.x, acc[1] + ba.y, acc[2] + ba.z, acc[3] + ba.w);
    float4 o1 = make_float4(acc[4] + bb.x, acc[5] + bb.y, acc[6] + bb.z, acc[7] + bb.w);
    reinterpret_cast<float4*>(out)[n * 4 + q * 2]     = o0;
    reinterpret_cast<float4*>(out)[n * 4 + q * 2 + 1] = o1;

    // restore scratch state for the next replay (reads of g_deg happened above)
    if (q == 0) g_deg[n] = 0;
    if (blockIdx.x == 0 && threadIdx.x < NBLK) g_flag[threadIdx.x] = 0;
}

// ---------------------------------------------------------------------------
extern "C" void kernel_launch(void* const* d_in, const int* in_sizes, int n_in,
                              void* d_out, int out_size)
{
    const float* X    = (const float*)d_in[0];
    const float* ew   = (const float*)d_in[1];
    const float* W1   = (const float*)d_in[2];
    const float* b1   = (const float*)d_in[3];
    const float* W2   = (const float*)d_in[4];
    const float* b2   = (const float*)d_in[5];
    const int*   esrc = (const int*)d_in[6];
    const int*   edst = (const int*)d_in[7];
    float* out = (float*)d_out;

    static cudaStream_t s1 = 0;
    static cudaEvent_t eFork = 0, eJoin = 0;
    static bool init_done = false;
    if (!init_done) {
        cudaStreamCreateWithFlags(&s1, cudaStreamNonBlocking);
        cudaEventCreateWithFlags(&eFork, cudaEventDisableTiming);
        cudaEventCreateWithFlags(&eJoin, cudaEventDisableTiming);
        init_done = true;
    }

    // Fork: gemm1 (independent of CSR build) on s1
    cudaEventRecord(eFork, 0);
    cudaStreamWaitEvent(s1, eFork, 0);
    gemm1_kernel<<<(NN + 63) / 64, 256, 0, s1>>>(X, W1);

    // CSR build on main stream (g_deg/g_flag pre-zeroed by previous call / load)
    hist_kernel<<<(NE + 255) / 256, 256>>>(edst);
    scan_fused_kernel<<<NBLK, 1024>>>();
    reorder_kernel<<<(NE / 4 + 255) / 256, 256>>>(esrc, edst, ew);

    // Join: aggregation needs both H1 and the CSR
    cudaEventRecord(eJoin, s1);
    cudaStreamWaitEvent(0, eJoin, 0);

    agg1_fused_kernel<<<NN * 8 / 256, 256>>>(b1, W2);
    agg2_kernel<<<(NN * 2 + 255) / 256, 256>>>(b2, out);
}

// round 9
// speedup vs baseline: 1.1912x; 1.0006x over previous
#include <cuda_runtime.h>
#include <cuda_fp16.h>
#include <cuda_bf16.h>
#include <mma.h>
using namespace nvcuda;

// Problem constants (fixed dataset)
#define NN 100000      // nodes
#define NE 1600000     // edges
#define IN_F 128
#define H_F 64
#define C_F 16
#define NBLK ((NN + 1023) / 1024)   // 98 scan blocks
#define DBIN 64                     // degree clamp bins

// Scratch (static device arrays; no allocation allowed)
__device__ uint4 g_H1h[NN * 8];       // X @ W1, fp16 (64 halves = 8 uint4 per row)
__device__ uint4 g_H2h[NN * 2];       // fused layer-2 features, fp16 (16 halves)
__device__ int   g_deg[NN];           // in-degree per dst (zeroed at end of agg2)
__device__ int   g_off[NN];           // CSR row offsets
__device__ int   g_cursor[NN];        // fill cursor for reorder
__device__ int   g_blocksum[NBLK];
__device__ int   g_flag[NBLK];        // publication flags (zeroed at end of agg2)
__device__ int2  g_csr[NE];           // (src, weight-bits) sorted by dst
__device__ int   g_dhist[DBIN];       // degree-bin counts (zeroed at end of agg2)
__device__ int   g_dcur[DBIN];        // degree-bin cursors (zeroed at end of agg2)
__device__ int   g_perm[NN];          // nodes sorted by degree bin

// ---------------------------------------------------------------------------
__global__ void hist_kernel(const int* __restrict__ edst) {
    int e = blockIdx.x * blockDim.x + threadIdx.x;
    if (e < NE) atomicAdd(&g_deg[__ldg(&edst[e])], 1);
}

// Fused scan: per-block exclusive scan (1024/block) + cross-block lookback.
__global__ __launch_bounds__(1024) void scan_fused_kernel() {
    __shared__ int warpsums[32];
    __shared__ int s_part[32];
    __shared__ int s_boff;
    const int t = threadIdx.x, lane = t & 31, wid = t >> 5;
    const int b = blockIdx.x;
    const int i = b * 1024 + t;

    int v = (i < NN) ? g_deg[i] : 0;
    int s = v;
    #pragma unroll
    for (int o = 1; o < 32; o <<= 1) {
        int nv = __shfl_up_sync(0xffffffffu, s, o);
        if (lane >= o) s += nv;
    }
    if (lane == 31) warpsums[wid] = s;
    __syncthreads();
    if (wid == 0) {
        int ws = warpsums[lane];
        int t2 = ws;
        #pragma unroll
        for (int o = 1; o < 32; o <<= 1) {
            int nv = __shfl_up_sync(0xffffffffu, t2, o);
            if (lane >= o) t2 += nv;
        }
        warpsums[lane] = t2 - ws;
        if (lane == 31) {
            g_blocksum[b] = t2;
            __threadfence();
            atomicExch(&g_flag[b], 1);
        }
    }
    __syncthreads();

    int part = 0;
    if (t < b) {
        while (atomicAdd(&g_flag[t], 0) == 0) { }
        part = g_blocksum[t];
    }
    #pragma unroll
    for (int o = 16; o > 0; o >>= 1) part += __shfl_down_sync(0xffffffffu, part, o);
    if (lane == 0) s_part[wid] = part;
    __syncthreads();
    if (t == 0) {
        int acc = 0;
        #pragma unroll
        for (int w = 0; w < 32; w++) acc += s_part[w];
        s_boff = acc;
    }
    __syncthreads();

    if (i < NN) {
        int val = warpsums[wid] + s - v + s_boff;
        g_off[i] = val;
        g_cursor[i] = val;
    }
}

// reorder (scalar: measured faster than the 4-wide variant)
__global__ void reorder_kernel(const int* __restrict__ esrc,
                               const int* __restrict__ edst,
                               const float* __restrict__ ew) {
    int e = blockIdx.x * blockDim.x + threadIdx.x;
    if (e < NE) {
        int d = __ldg(&edst[e]);
        int p = atomicAdd(&g_cursor[d], 1);
        g_csr[p] = make_int2(__ldg(&esrc[e]), __float_as_int(__ldg(&ew[e])));
    }
}

// ---------------------------------------------------------------------------
// Degree-bin counting sort of node ids (runs on side stream, overlapped
// with reorder). Bin = min(deg, 63).
__global__ __launch_bounds__(256) void dhist_kernel() {
    __shared__ int sh[DBIN];
    const int t = threadIdx.x;
    if (t < DBIN) sh[t] = 0;
    __syncthreads();
    int n = blockIdx.x * 256 + t;
    if (n < NN) atomicAdd(&sh[min(g_deg[n], DBIN - 1)], 1);
    __syncthreads();
    if (t < DBIN && sh[t] > 0) atomicAdd(&g_dhist[t], sh[t]);
}

__global__ void dscan_kernel() {
    // 64-bin exclusive scan, single thread in smem (trivial)
    if (threadIdx.x == 0) {
        int run = 0;
        for (int b = 0; b < DBIN; b++) {
            int c = g_dhist[b];
            g_dcur[b] = run;
            run += c;
        }
    }
}

__global__ __launch_bounds__(256) void dscatter_kernel() {
    __shared__ int scnt[DBIN];
    __shared__ int sbase[DBIN];
    const int t = threadIdx.x;
    if (t < DBIN) scnt[t] = 0;
    __syncthreads();
    int n = blockIdx.x * 256 + t;
    int d = 0, my = 0;
    if (n < NN) {
        d = min(g_deg[n], DBIN - 1);
        my = atomicAdd(&scnt[d], 1);
    }
    __syncthreads();
    if (t < DBIN && scnt[t] > 0) sbase[t] = atomicAdd(&g_dcur[t], scnt[t]);
    __syncthreads();
    if (n < NN) g_perm[sbase[d] + my] = n;
}

// ---------------------------------------------------------------------------
// GEMM1 (tensor cores): H1[NN,64] = X[NN,128] @ W1[128,64]
#define XS_LD 136
#define WS_LD 72
__global__ __launch_bounds__(256) void gemm1_kernel(
    const float* __restrict__ X, const float* __restrict__ W1)
{
    __shared__ __align__(16) char smbuf[64 * XS_LD * 2 + 128 * WS_LD * 2];
    __half* Xs = reinterpret_cast<__half*>(smbuf);
    __half* Ws = reinterpret_cast<__half*>(smbuf + 64 * XS_LD * 2);
    float*  Cs = reinterpret_cast<float*>(smbuf);

    const int t = threadIdx.x;
    const int row0 = blockIdx.x * 64;

    const float4* Xv = reinterpret_cast<const float4*>(X);
    #pragma unroll
    for (int i = 0; i < 8; i++) {
        int idx = t + i * 256;
        int r = idx >> 5;
        int c4 = idx & 31;
        int grow = row0 + r;
        float4 v = make_float4(0.f, 0.f, 0.f, 0.f);
        if (grow < NN) v = Xv[(long long)grow * 32 + c4];
        __half2* dst = reinterpret_cast<__half2*>(&Xs[r * XS_LD + c4 * 4]);
        dst[0] = __floats2half2_rn(v.x, v.y);
        dst[1] = __floats2half2_rn(v.z, v.w);
    }
    const float4* Wv = reinterpret_cast<const float4*>(W1);
    #pragma unroll
    for (int i = 0; i < 8; i++) {
        int idx = t + i * 256;
        int k = idx >> 4;
        int c4 = idx & 15;
        float4 v = Wv[k * 16 + c4];
        __half2* dst = reinterpret_cast<__half2*>(&Ws[k * WS_LD + c4 * 4]);
        dst[0] = __floats2half2_rn(v.x, v.y);
        dst[1] = __floats2half2_rn(v.z, v.w);
    }
    __syncthreads();

    const int w = t >> 5;
    const int m_tile = w >> 1;
    const int n0 = (w & 1) * 32;

    wmma::fragment<wmma::accumulator, 16, 16, 16, float> acc0, acc1;
    wmma::fill_fragment(acc0, 0.f);
    wmma::fill_fragment(acc1, 0.f);

    #pragma unroll
    for (int k = 0; k < 8; k++) {
        wmma::fragment<wmma::matrix_a, 16, 16, 16, __half, wmma::row_major> a;
        wmma::load_matrix_sync(a, Xs + m_tile * 16 * XS_LD + k * 16, XS_LD);
        wmma::fragment<wmma::matrix_b, 16, 16, 16, __half, wmma::row_major> b0, b1;
        wmma::load_matrix_sync(b0, Ws + k * 16 * WS_LD + n0, WS_LD);
        wmma::load_matrix_sync(b1, Ws + k * 16 * WS_LD + n0 + 16, WS_LD);
        wmma::mma_sync(acc0, a, b0, acc0);
        wmma::mma_sync(acc1, a, b1, acc1);
    }
    __syncthreads();

    wmma::store_matrix_sync(Cs + m_tile * 16 * 64 + n0, acc0, 64, wmma::mem_row_major);
    wmma::store_matrix_sync(Cs + m_tile * 16 * 64 + n0 + 16, acc1, 64, wmma::mem_row_major);
    __syncthreads();

    __half2* H1 = reinterpret_cast<__half2*>(g_H1h);
    #pragma unroll
    for (int i = 0; i < 8; i++) {
        int idx = t + i * 256;
        int r = idx >> 5;
        int c2 = idx & 31;
        int grow = row0 + r;
        if (grow < NN) {
            float lo = Cs[r * 64 + c2 * 2];
            float hi = Cs[r * 64 + c2 * 2 + 1];
            H1[grow * 32 + c2] = __floats2half2_rn(lo, hi);
        }
    }
}

// ---------------------------------------------------------------------------
__device__ __forceinline__ void fma_h8(float* acc, uint4 v, float w) {
    const __half2* hp = reinterpret_cast<const __half2*>(&v);
    #pragma unroll
    for (int i = 0; i < 4; i++) {
        float2 f = __half22float2(hp[i]);
        acc[2*i]   = fmaf(f.x, w, acc[2*i]);
        acc[2*i+1] = fmaf(f.y, w, acc[2*i+1]);
    }
}

// Fused aggregation + GEMM2 (8 threads/node, nodes walked in degree order).
__global__ __launch_bounds__(256) void agg1_fused_kernel(
    const float* __restrict__ b1, const float* __restrict__ W2)
{
    __shared__ float Ws[64 * 16];
    __shared__ float b1s[64];
    __shared__ float hbuf[32 * 68];

    const int t = threadIdx.x;
    #pragma unroll
    for (int i = 0; i < 4; i++) Ws[t + i * 256] = W2[t + i * 256];
    if (t < 64) b1s[t] = b1[t];
    __syncthreads();

    const int gt = blockIdx.x * 256 + t;
    const int n = __ldg(&g_perm[gt >> 3]);   // degree-sorted node
    const int q = gt & 7;
    const int g = t >> 3;

    const int start = g_off[n];
    const int cnt   = g_deg[n];

    float acc[8];
    #pragma unroll
    for (int i = 0; i < 8; i++) acc[i] = 0.f;

    int j = 0;
    if ((start & 1) && j < cnt) {
        int2 ed = __ldg(&g_csr[start]);
        fma_h8(acc, __ldg(&g_H1h[ed.x * 8 + q]), __int_as_float(ed.y));
        j = 1;
    }
    const int4* csr4 = reinterpret_cast<const int4*>(g_csr + start + j);
    int rem = cnt - j;
    int quads = rem >> 2;
    for (int k = 0; k < quads; k++) {
        int4 eA = __ldg(&csr4[2*k]);
        int4 eB = __ldg(&csr4[2*k + 1]);
        uint4 v0 = __ldg(&g_H1h[eA.x * 8 + q]);
        uint4 v1 = __ldg(&g_H1h[eA.z * 8 + q]);
        uint4 v2 = __ldg(&g_H1h[eB.x * 8 + q]);
        uint4 v3 = __ldg(&g_H1h[eB.z * 8 + q]);
        fma_h8(acc, v0, __int_as_float(eA.y));
        fma_h8(acc, v1, __int_as_float(eA.w));
        fma_h8(acc, v2, __int_as_float(eB.y));
        fma_h8(acc, v3, __int_as_float(eB.w));
    }
    j += quads << 2;
    for (; j < cnt; j++) {
        int2 ed = __ldg(&g_csr[start + j]);
        fma_h8(acc, __ldg(&g_H1h[ed.x * 8 + q]), __int_as_float(ed.y));
    }

    #pragma unroll
    for (int i = 0; i < 8; i++) {
        float h = fmaxf(acc[i] + b1s[q * 8 + i], 0.f);
        hbuf[g * 68 + q * 8 + i] = h;
    }
    __syncwarp();

    float p0 = 0.f, p1 = 0.f;
    const float4* hb4 = reinterpret_cast<const float4*>(&hbuf[g * 68]);
    const float2* Ws2 = reinterpret_cast<const float2*>(Ws);
    #pragma unroll
    for (int k4 = 0; k4 < 16; k4++) {
        float4 hv = hb4[k4];
        float2 w0 = Ws2[(k4 * 4 + 0) * 8 + q];
        float2 w1 = Ws2[(k4 * 4 + 1) * 8 + q];
        float2 w2 = Ws2[(k4 * 4 + 2) * 8 + q];
        float2 w3 = Ws2[(k4 * 4 + 3) * 8 + q];
        p0 = fmaf(hv.x, w0.x, p0); p1 = fmaf(hv.x, w0.y, p1);
        p0 = fmaf(hv.y, w1.x, p0); p1 = fmaf(hv.y, w1.y, p1);
        p0 = fmaf(hv.z, w2.x, p0); p1 = fmaf(hv.z, w2.y, p1);
        p0 = fmaf(hv.w, w3.x, p0); p1 = fmaf(hv.w, w3.y, p1);
    }
    reinterpret_cast<__half2*>(g_H2h)[n * 8 + q] = __floats2half2_rn(p0, p1);
}

// ---------------------------------------------------------------------------
// Aggregation layer 2 (2 threads/node, degree-ordered). Restores scratch.
__global__ __launch_bounds__(256) void agg2_kernel(
    const float* __restrict__ b2, float* __restrict__ out)
{
    int gt = blockIdx.x * blockDim.x + threadIdx.x;
    int ni = gt >> 1;
    int q = gt & 1;
    if (ni >= NN) return;
    const int n = __ldg(&g_perm[ni]);
    const int start = g_off[n];
    const int cnt   = g_deg[n];

    float acc[8];
    #pragma unroll
    for (int i = 0; i < 8; i++) acc[i] = 0.f;

    int j = 0;
    if ((start & 1) && j < cnt) {
        int2 ed = __ldg(&g_csr[start]);
        fma_h8(acc, __ldg(&g_H2h[ed.x * 2 + q]), __int_as_float(ed.y));
        j = 1;
    }
    const int4* csr4 = reinterpret_cast<const int4*>(g_csr + start + j);
    int rem = cnt - j;
    int quads = rem >> 2;
    for (int k = 0; k < quads; k++) {
        int4 eA = __ldg(&csr4[2*k]);
        int4 eB = __ldg(&csr4[2*k + 1]);
        uint4 v0 = __ldg(&g_H2h[eA.x * 2 + q]);
        uint4 v1 = __ldg(&g_H2h[eA.z * 2 + q]);
        uint4 v2 = __ldg(&g_H2h[eB.x * 2 + q]);
        uint4 v3 = __ldg(&g_H2h[eB.z * 2 + q]);
        fma_h8(acc, v0, __int_as_float(eA.y));
        fma_h8(acc, v1, __int_as_float(eA.w));
        fma_h8(acc, v2, __int_as_float(eB.y));
        fma_h8(acc, v3, __int_as_float(eB.w));
    }
    j += quads << 2;
    for (; j < cnt; j++) {
        int2 ed = __ldg(&g_csr[start + j]);
        fma_h8(acc, __ldg(&g_H2h[ed.x * 2 + q]), __int_as_float(ed.y));
    }

    const float4* b2v = reinterpret_cast<const float4*>(b2);
    float4 ba = __ldg(&b2v[q * 2]);
    float4 bb = __ldg(&b2v[q * 2 + 1]);
    float4 o0 = make_float4(acc[0] + ba.x, acc[1] + ba.y, acc[2] + ba.z, acc[3] + ba.w);
    float4 o1 = make_float4(acc[4] + bb.x, acc[5] + bb.y, acc[6] + bb.z, acc[7] + bb.w);
    reinterpret_cast<float4*>(out)[n * 4 + q * 2]     = o0;
    reinterpret_cast<float4*>(out)[n * 4 + q * 2 + 1] = o1;

    // restore scratch state for the next replay
    if (q == 0) g_deg[n] = 0;
    if (blockIdx.x == 0) {
        int t = threadIdx.x;
        if (t < NBLK) g_flag[t] = 0;
        if (t < DBIN) { g_dhist[t] = 0; g_dcur[t] = 0; }
    }
}

// ---------------------------------------------------------------------------
extern "C" void kernel_launch(void* const* d_in, const int* in_sizes, int n_in,
                              void* d_out, int out_size)
{
    const float* X    = (const float*)d_in[0];
    const float* ew   = (const float*)d_in[1];
    const float* W1   = (const float*)d_in[2];
    const float* b1   = (const float*)d_in[3];
    const float* W2   = (const float*)d_in[4];
    const float* b2   = (const float*)d_in[5];
    const int*   esrc = (const int*)d_in[6];
    const int*   edst = (const int*)d_in[7];
    float* out = (float*)d_out;

    static cudaStream_t s1 = 0;
    static cudaEvent_t eFork = 0, eHist = 0, eJoin = 0;
    static bool init_done = false;
    if (!init_done) {
        cudaStreamCreateWithFlags(&s1, cudaStreamNonBlocking);
        cudaEventCreateWithFlags(&eFork, cudaEventDisableTiming);
        cudaEventCreateWithFlags(&eHist, cudaEventDisableTiming);
        cudaEventCreateWithFlags(&eJoin, cudaEventDisableTiming);
        init_done = true;
    }

    // Fork: gemm1 on s1 (independent of everything on main stream)
    cudaEventRecord(eFork, 0);
    cudaStreamWaitEvent(s1, eFork, 0);
    gemm1_kernel<<<(NN + 63) / 64, 256, 0, s1>>>(X, W1);

    // Main stream: degree histogram
    hist_kernel<<<(NE + 255) / 256, 256>>>(edst);
    cudaEventRecord(eHist, 0);

    // Main stream continues CSR: scan + reorder
    scan_fused_kernel<<<NBLK, 1024>>>();
    reorder_kernel<<<(NE + 255) / 256, 256>>>(esrc, edst, ew);

    // Side stream: degree-bin sort (needs only g_deg) — overlaps reorder
    cudaStreamWaitEvent(s1, eHist, 0);
    dhist_kernel<<<(NN + 255) / 256, 256, 0, s1>>>();
    dscan_kernel<<<1, 32, 0, s1>>>();
    dscatter_kernel<<<(NN + 255) / 256, 256, 0, s1>>>();
    cudaEventRecord(eJoin, s1);

    // Join: aggregation needs H1, CSR, and perm
    cudaStreamWaitEvent(0, eJoin, 0);

    agg1_fused_kernel<<<NN * 8 / 256, 256>>>(b1, W2);
    agg2_kernel<<<(NN * 2 + 255) / 256, 256>>>(b2, out);
}